// round 5
// baseline (speedup 1.0000x reference)
#include <cuda_runtime.h>

typedef unsigned long long ull;

// ---------------------------------------------------------------- constants
#define MTOT 200704          // total tokens = 4*16*56*56 = 2048 windows * 98
#define NWIN 2048
#define NTOK 98
#define CCH  128
#define NHD  4
#define HDIM 32
#define LWIN 512
#define MREL 507
#define MLPH 512
#define SCALE_Q 0.17677669529663687f   // 32^-0.5

// ---------------------------------------------------------------- scratch
// (no cudaMalloc allowed -> __device__ globals; buffers are reused:
//  g_win: LN1 output (window order), then attention output
//  g_q  : scaled Q, then LN2 output (xn2)
__device__ __align__(16) float g_win[MTOT * CCH];
__device__ __align__(16) float g_q[MTOT * CCH];
__device__ __align__(16) float g_k[MTOT * CCH];
__device__ __align__(16) float g_v[MTOT * CCH];
__device__ __align__(16) float g_xres[MTOT * CCH];
__device__ __align__(16) float g_h[MTOT * MLPH];
__device__ __align__(16) float g_bias[NHD * NTOK * NTOK];

// ---------------------------------------------------------------- helpers
__device__ __forceinline__ ull pack2(float a) {
    ull r; asm("mov.b64 %0, {%1, %1};" : "=l"(r) : "f"(a)); return r;
}
__device__ __forceinline__ float2 unpack2(ull v) {
    float2 f; asm("mov.b64 {%0, %1}, %2;" : "=f"(f.x), "=f"(f.y) : "l"(v)); return f;
}
__device__ __forceinline__ void ffma2(ull &acc, ull a, ull b) {
    asm("fma.rn.f32x2 %0, %1, %2, %0;" : "+l"(acc) : "l"(a), "l"(b));
}
__device__ __forceinline__ float gelu_f(float v) {
    return 0.5f * v * (1.0f + erff(v * 0.70710678118654752f));
}

// window token (wi, n)  <->  flat index into the ORIGINAL x layout
// (applies shift +SS both for the forward gather and the inverse scatter)
__device__ __forceinline__ size_t win_to_src(int wi, int n) {
    int b  = wi >> 9;          // / 512
    int l  = wi & 511;
    int wt = l >> 6, wh = (l >> 3) & 7, wwb = l & 7;
    int nt = n / 49, rem = n % 49, nh2 = rem / 7, nw2 = rem % 7;
    int ts = wt * 2 + nt, hs = wh * 7 + nh2, wsd = wwb * 7 + nw2;
    int t  = (ts + 1) & 15;
    int hh = hs + 3;  if (hh >= 56) hh -= 56;
    int ww = wsd + 3; if (ww >= 56) ww -= 56;
    return ((((size_t)b * 16 + t) * 56 + hh) * 56 + ww) * (size_t)CCH;
}

// ---------------------------------------------------------------- GEMM core
// C[128x128 tile] = A[M x K] * B[K x N], A,B row-major, fp32, f32x2 FMAs.
// blockIdx.y = row tile, colBase given. 256 threads, 8x8 per thread.
// Thread columns: colBase + tx*4 + {0..3} and + 64 + {0..3}.
template<int K>
__device__ __forceinline__ void gemm_core(const float* __restrict__ A,
                                          const float* __restrict__ B,
                                          int N, int rowBase, int colBase,
                                          ull acc[8][4]) {
    __shared__ float As[128][8];
    __shared__ float Bs[8][128];
    const int tid = threadIdx.x;
    const int tx = tid & 15, ty = tid >> 4;

#pragma unroll
    for (int r = 0; r < 8; r++)
#pragma unroll
        for (int c = 0; c < 4; c++) acc[r][c] = 0ULL;

    const int arow = tid >> 1;
    const int acol = (tid & 1) * 4;
    const int brow = tid >> 5;
    const int bcol = (tid & 31) * 4;

    for (int k0 = 0; k0 < K; k0 += 8) {
        float4 av = *(const float4*)(A + (size_t)(rowBase + arow) * K + k0 + acol);
        float4 bv = *(const float4*)(B + (size_t)(k0 + brow) * N + colBase + bcol);
        __syncthreads();
        *(float4*)&As[arow][acol] = av;
        *(float4*)&Bs[brow][bcol] = bv;
        __syncthreads();
#pragma unroll
        for (int kk = 0; kk < 8; kk++) {
            ull rm[8];
#pragma unroll
            for (int r = 0; r < 8; r++) rm[r] = pack2(As[(ty << 3) + r][kk]);
            ulonglong2 b0 = *(const ulonglong2*)&Bs[kk][tx * 4];
            ulonglong2 b1 = *(const ulonglong2*)&Bs[kk][tx * 4 + 64];
#pragma unroll
            for (int r = 0; r < 8; r++) {
                ffma2(acc[r][0], rm[r], b0.x);
                ffma2(acc[r][1], rm[r], b0.y);
                ffma2(acc[r][2], rm[r], b1.x);
                ffma2(acc[r][3], rm[r], b1.y);
            }
        }
    }
}

// column offset for acc pair c2 (pair holds cols j0, j0+1)
__device__ __forceinline__ int pair_col(int tx, int c2) {
    return (tx << 2) + ((c2 >> 1) << 6) + ((c2 & 1) << 1);
}

// ---------------------------------------------------------------- kernels
// 0) rel-pos bias gather: g_bias[h][n*98+m] = rpe[h][idx[n*98+m]]
__global__ void bias_kernel(const float* __restrict__ rpe, const int* __restrict__ idx) {
    int i = blockIdx.x * 256 + threadIdx.x;
    if (i < NHD * NTOK * NTOK) {
        int h = i / (NTOK * NTOK), e = i % (NTOK * NTOK);
        g_bias[i] = rpe[h * MREL + idx[e]];
    }
}

// 1) LN1 + cyclic shift + window partition.  One warp per token.
__global__ __launch_bounds__(256) void ln1_kernel(const float* __restrict__ x,
                                                  const float* __restrict__ g,
                                                  const float* __restrict__ bb) {
    int warp = threadIdx.x >> 5, lane = threadIdx.x & 31;
    int tk = blockIdx.x * 8 + warp;            // token in window order
    int wi = tk / NTOK, n = tk % NTOK;
    const float* src = x + win_to_src(wi, n);
    float4 v = *(const float4*)(src + lane * 4);
    float s  = v.x + v.y + v.z + v.w;
    float sq = v.x * v.x + v.y * v.y + v.z * v.z + v.w * v.w;
#pragma unroll
    for (int o = 16; o; o >>= 1) {
        s  += __shfl_xor_sync(0xffffffffu, s, o);
        sq += __shfl_xor_sync(0xffffffffu, sq, o);
    }
    float mu = s * (1.0f / 128.0f);
    float var = sq * (1.0f / 128.0f) - mu * mu;
    float rstd = rsqrtf(var + 1e-5f);
    float4 gg = *(const float4*)(g + lane * 4);
    float4 b4 = *(const float4*)(bb + lane * 4);
    float4 o4;
    o4.x = (v.x - mu) * rstd * gg.x + b4.x;
    o4.y = (v.y - mu) * rstd * gg.y + b4.y;
    o4.z = (v.z - mu) * rstd * gg.z + b4.z;
    o4.w = (v.w - mu) * rstd * gg.w + b4.w;
    *(float4*)(g_win + (size_t)tk * CCH + lane * 4) = o4;
}

// 2) QKV GEMM: g_win[200704x128] @ w_qkv[128x384] + b -> scatter q(k)(v)
__global__ __launch_bounds__(256) void qkv_gemm(const float* __restrict__ W,
                                                const float* __restrict__ bias) {
    ull acc[8][4];
    int rowBase = blockIdx.y * 128, colBase = blockIdx.x * 128;
    gemm_core<128>(g_win, W, 384, rowBase, colBase, acc);
    int tx = threadIdx.x & 15, ty = threadIdx.x >> 4;
#pragma unroll
    for (int r = 0; r < 8; r++) {
        int row = rowBase + (ty << 3) + r;
        int wi = row / NTOK, n = row % NTOK;
#pragma unroll
        for (int c2 = 0; c2 < 4; c2++) {
            float2 f = unpack2(acc[r][c2]);
            int j0 = colBase + pair_col(tx, c2);
#pragma unroll
            for (int p = 0; p < 2; p++) {
                int j = j0 + p;
                float val = (p ? f.y : f.x) + bias[j];
                int which = j >> 7, head = (j >> 5) & 3, hd = j & 31;
                int dst = (((wi << 2) + head) * NTOK + n) * HDIM + hd;
                if (which == 0)      g_q[dst] = val * SCALE_Q;
                else if (which == 1) g_k[dst] = val;
                else                 g_v[dst] = val;
            }
        }
    }
}

// 3) Attention per (window, head).  blockIdx.x = head, blockIdx.y = wi.
__global__ __launch_bounds__(128) void attn_kernel(const float* __restrict__ amask) {
    __shared__ float qs[NTOK][32];
    __shared__ float ks[NTOK][36];    // padded for conflict-free float4 col reads
    __shared__ float vs[NTOK][32];
    __shared__ float ps[4][NTOK][4];  // [warp][m][row-in-group]

    int head = blockIdx.x, wi = blockIdx.y;
    int l = wi & 511;
    int tid = threadIdx.x, warp = tid >> 5, lane = tid & 31;
    size_t base = (size_t)((wi << 2) + head) * NTOK * HDIM;
    const float* qg = g_q + base;
    const float* kg = g_k + base;
    const float* vg = g_v + base;

    for (int i = tid; i < NTOK * 8; i += 128) {  // 784 float4 per tensor
        float4 qv = *(const float4*)(qg + i * 4);
        float4 kv = *(const float4*)(kg + i * 4);
        float4 vv = *(const float4*)(vg + i * 4);
        *(float4*)(&qs[0][0] + i * 4) = qv;
        *(float4*)(&vs[0][0] + i * 4) = vv;
        int m = i >> 3, dd = (i & 7) * 4;
        *(float4*)&ks[m][dd] = kv;
    }
    __syncthreads();

    const float* bm_b = g_bias + head * (NTOK * NTOK);
    const float* bm_m = amask + (size_t)l * (NTOK * NTOK);

    for (int gidx = warp; gidx < 25; gidx += 4) {
        int n0 = gidx * 4;
        ull accp[4][4];
#pragma unroll
        for (int r = 0; r < 4; r++)
#pragma unroll
            for (int mi = 0; mi < 4; mi++) accp[r][mi] = 0ULL;

#pragma unroll
        for (int d0 = 0; d0 < 8; d0++) {
            ulonglong2 q2[4];
#pragma unroll
            for (int r = 0; r < 4; r++) {
                int nc = n0 + r; if (nc > 97) nc = 97;
                q2[r] = *(const ulonglong2*)&qs[nc][d0 * 4];
            }
#pragma unroll
            for (int mi = 0; mi < 4; mi++) {
                int m = lane + (mi << 5);
                if (m < NTOK) {
                    ulonglong2 k2 = *(const ulonglong2*)&ks[m][d0 * 4];
#pragma unroll
                    for (int r = 0; r < 4; r++) {
                        ffma2(accp[r][mi], q2[r].x, k2.x);
                        ffma2(accp[r][mi], q2[r].y, k2.y);
                    }
                }
            }
        }

        // softmax per row
#pragma unroll
        for (int r = 0; r < 4; r++) {
            int n = n0 + r;
            if (n < NTOK) {
                float sc[4];
#pragma unroll
                for (int mi = 0; mi < 4; mi++) {
                    int m = lane + (mi << 5);
                    if (m < NTOK) {
                        float2 f = unpack2(accp[r][mi]);
                        sc[mi] = f.x + f.y + bm_b[n * NTOK + m] + bm_m[n * NTOK + m];
                    } else sc[mi] = -1e30f;
                }
                float mx = fmaxf(fmaxf(sc[0], sc[1]), fmaxf(sc[2], sc[3]));
#pragma unroll
                for (int o = 16; o; o >>= 1) mx = fmaxf(mx, __shfl_xor_sync(0xffffffffu, mx, o));
                float ssum = 0.f;
#pragma unroll
                for (int mi = 0; mi < 4; mi++) {
                    int m = lane + (mi << 5);
                    if (m < NTOK) { float e = __expf(sc[mi] - mx); sc[mi] = e; ssum += e; }
                }
#pragma unroll
                for (int o = 16; o; o >>= 1) ssum += __shfl_xor_sync(0xffffffffu, ssum, o);
                float inv = 1.0f / ssum;
#pragma unroll
                for (int mi = 0; mi < 4; mi++) {
                    int m = lane + (mi << 5);
                    if (m < NTOK) ps[warp][m][r] = sc[mi] * inv;
                }
            } else {
#pragma unroll
                for (int mi = 0; mi < 4; mi++) {
                    int m = lane + (mi << 5);
                    if (m < NTOK) ps[warp][m][r] = 0.f;
                }
            }
        }
        __syncwarp();

        // P @ V : lane = head-dim, 4 rows at once via f32x2
        ull o2a = 0ULL, o2b = 0ULL;
        for (int m = 0; m < NTOK; m++) {
            float vv = vs[m][lane];
            ulonglong2 pp = *(const ulonglong2*)&ps[warp][m][0];
            ull v2 = pack2(vv);
            ffma2(o2a, pp.x, v2);
            ffma2(o2b, pp.y, v2);
        }
        float2 oa = unpack2(o2a), ob = unpack2(o2b);
        float ov[4] = {oa.x, oa.y, ob.x, ob.y};
#pragma unroll
        for (int r = 0; r < 4; r++) {
            int n = n0 + r;
            if (n < NTOK)
                g_win[((size_t)wi * NTOK + n) * CCH + head * HDIM + lane] = ov[r];
        }
        __syncwarp();
    }
}

// 4) proj GEMM + un-partition + reverse shift + residual -> g_xres
__global__ __launch_bounds__(256) void proj_gemm(const float* __restrict__ W,
                                                 const float* __restrict__ bias,
                                                 const float* __restrict__ x) {
    ull acc[8][4];
    int rowBase = blockIdx.y * 128;
    gemm_core<128>(g_win, W, 128, rowBase, 0, acc);
    int tx = threadIdx.x & 15, ty = threadIdx.x >> 4;
#pragma unroll
    for (int r = 0; r < 8; r++) {
        int row = rowBase + (ty << 3) + r;
        int wi = row / NTOK, n = row % NTOK;
        size_t dst = win_to_src(wi, n);
#pragma unroll
        for (int c2 = 0; c2 < 4; c2++) {
            float2 f = unpack2(acc[r][c2]);
            int j0 = pair_col(tx, c2);
            g_xres[dst + j0]     = x[dst + j0]     + f.x + bias[j0];
            g_xres[dst + j0 + 1] = x[dst + j0 + 1] + f.y + bias[j0 + 1];
        }
    }
}

// 5) LN2: g_xres -> g_q (reused as xn2), natural token order
__global__ __launch_bounds__(256) void ln2_kernel(const float* __restrict__ g,
                                                  const float* __restrict__ bb) {
    int warp = threadIdx.x >> 5, lane = threadIdx.x & 31;
    int tk = blockIdx.x * 8 + warp;
    const float* src = g_xres + (size_t)tk * CCH;
    float4 v = *(const float4*)(src + lane * 4);
    float s  = v.x + v.y + v.z + v.w;
    float sq = v.x * v.x + v.y * v.y + v.z * v.z + v.w * v.w;
#pragma unroll
    for (int o = 16; o; o >>= 1) {
        s  += __shfl_xor_sync(0xffffffffu, s, o);
        sq += __shfl_xor_sync(0xffffffffu, sq, o);
    }
    float mu = s * (1.0f / 128.0f);
    float var = sq * (1.0f / 128.0f) - mu * mu;
    float rstd = rsqrtf(var + 1e-5f);
    float4 gg = *(const float4*)(g + lane * 4);
    float4 b4 = *(const float4*)(bb + lane * 4);
    float4 o4;
    o4.x = (v.x - mu) * rstd * gg.x + b4.x;
    o4.y = (v.y - mu) * rstd * gg.y + b4.y;
    o4.z = (v.z - mu) * rstd * gg.z + b4.z;
    o4.w = (v.w - mu) * rstd * gg.w + b4.w;
    *(float4*)(g_q + (size_t)tk * CCH + lane * 4) = o4;
}

// 6) FC1 GEMM + exact GELU -> g_h
__global__ __launch_bounds__(256) void fc1_gemm(const float* __restrict__ W,
                                                const float* __restrict__ bias) {
    ull acc[8][4];
    int rowBase = blockIdx.y * 128, colBase = blockIdx.x * 128;
    gemm_core<128>(g_q, W, MLPH, rowBase, colBase, acc);
    int tx = threadIdx.x & 15, ty = threadIdx.x >> 4;
#pragma unroll
    for (int r = 0; r < 8; r++) {
        int row = rowBase + (ty << 3) + r;
        float* hrow = g_h + (size_t)row * MLPH;
#pragma unroll
        for (int c2 = 0; c2 < 4; c2++) {
            float2 f = unpack2(acc[r][c2]);
            int j0 = colBase + pair_col(tx, c2);
            hrow[j0]     = gelu_f(f.x + bias[j0]);
            hrow[j0 + 1] = gelu_f(f.y + bias[j0 + 1]);
        }
    }
}

// 7) FC2 GEMM + final residual -> d_out
__global__ __launch_bounds__(256) void fc2_gemm(const float* __restrict__ W,
                                                const float* __restrict__ bias,
                                                float* __restrict__ out) {
    ull acc[8][4];
    int rowBase = blockIdx.y * 128;
    gemm_core<512>(g_h, W, CCH, rowBase, 0, acc);
    int tx = threadIdx.x & 15, ty = threadIdx.x >> 4;
#pragma unroll
    for (int r = 0; r < 8; r++) {
        int row = rowBase + (ty << 3) + r;
        size_t off = (size_t)row * CCH;
#pragma unroll
        for (int c2 = 0; c2 < 4; c2++) {
            float2 f = unpack2(acc[r][c2]);
            int j0 = pair_col(tx, c2);
            out[off + j0]     = g_xres[off + j0]     + f.x + bias[j0];
            out[off + j0 + 1] = g_xres[off + j0 + 1] + f.y + bias[j0 + 1];
        }
    }
}

// ---------------------------------------------------------------- launch
extern "C" void kernel_launch(void* const* d_in, const int* in_sizes, int n_in,
                              void* d_out, int out_size) {
    const float* x      = (const float*)d_in[0];
    const float* g1     = (const float*)d_in[1];
    const float* b1     = (const float*)d_in[2];
    const float* w_qkv  = (const float*)d_in[3];
    const float* b_qkv  = (const float*)d_in[4];
    const float* rpe    = (const float*)d_in[5];
    const float* w_proj = (const float*)d_in[6];
    const float* b_proj = (const float*)d_in[7];
    const float* g2     = (const float*)d_in[8];
    const float* b2     = (const float*)d_in[9];
    const float* w_fc1  = (const float*)d_in[10];
    const float* b_fc1  = (const float*)d_in[11];
    const float* w_fc2  = (const float*)d_in[12];
    const float* b_fc2  = (const float*)d_in[13];
    const float* amask  = (const float*)d_in[14];
    const int*   rpidx  = (const int*)d_in[15];
    float* out = (float*)d_out;

    bias_kernel<<<(NHD * NTOK * NTOK + 255) / 256, 256>>>(rpe, rpidx);
    ln1_kernel<<<MTOT / 8, 256>>>(x, g1, b1);
    qkv_gemm<<<dim3(3, MTOT / 128), 256>>>(w_qkv, b_qkv);
    attn_kernel<<<dim3(NHD, NWIN), 128>>>(amask);
    proj_gemm<<<dim3(1, MTOT / 128), 256>>>(w_proj, b_proj, x);
    ln2_kernel<<<MTOT / 8, 256>>>(g2, b2);
    fc1_gemm<<<dim3(4, MTOT / 128), 256>>>(w_fc1, b_fc1);
    fc2_gemm<<<dim3(1, MTOT / 128), 256>>>(w_fc2, b_fc2, out);
}

// round 16
// speedup vs baseline: 2.5760x; 2.5760x over previous
#include <cuda_runtime.h>

typedef unsigned long long ull;
typedef unsigned int u32;

// ---------------------------------------------------------------- constants
#define MTOT 200704          // total tokens = 4*16*56*56 = 2048 windows * 98
#define NWIN 2048
#define NTOK 98
#define CCH  128
#define NHD  4
#define HDIM 32
#define MREL 507
#define MLPH 512
#define SCALE_Q 0.17677669529663687f   // 32^-0.5

// ---------------------------------------------------------------- scratch
// g_win: LN1 output (window order), then attention output
// g_q  : scaled Q, then LN2 output (xn2)
__device__ __align__(16) float g_win[MTOT * CCH];
__device__ __align__(16) float g_q[MTOT * CCH];
__device__ __align__(16) float g_k[MTOT * CCH];
__device__ __align__(16) float g_v[MTOT * CCH];
__device__ __align__(16) float g_xres[MTOT * CCH];
__device__ __align__(16) float g_h[MTOT * MLPH];
__device__ __align__(16) float g_bias[NHD * NTOK * NTOK];
// fp32 transposed weights [N][K]
__device__ __align__(16) float g_wqkvT[384 * 128];
__device__ __align__(16) float g_wprojT[128 * 128];
__device__ __align__(16) float g_wfc1T[512 * 128];
__device__ __align__(16) float g_wfc2T[128 * 512];

// ---------------------------------------------------------------- helpers
__device__ __forceinline__ ull pack2(float a) {
    ull r; asm("mov.b64 %0, {%1, %1};" : "=l"(r) : "f"(a)); return r;
}
__device__ __forceinline__ float2 unpack2(ull v) {
    float2 f; asm("mov.b64 {%0, %1}, %2;" : "=f"(f.x), "=f"(f.y) : "l"(v)); return f;
}
__device__ __forceinline__ void ffma2(ull &acc, ull a, ull b) {
    asm("fma.rn.f32x2 %0, %1, %2, %0;" : "+l"(acc) : "l"(a), "l"(b));
}
__device__ __forceinline__ float gelu_f(float v) {
    return 0.5f * v * (1.0f + erff(v * 0.70710678118654752f));
}
__device__ __forceinline__ u32 f2tf32(float f) {
    u32 r; asm("cvt.rna.tf32.f32 %0, %1;" : "=r"(r) : "f"(f)); return r;
}
__device__ __forceinline__ void mma_tf32(float c[4], const u32 a[4],
                                         u32 b0, u32 b1) {
    asm("mma.sync.aligned.m16n8k8.row.col.f32.tf32.tf32.f32 "
        "{%0,%1,%2,%3}, {%4,%5,%6,%7}, {%8,%9}, {%0,%1,%2,%3};"
        : "+f"(c[0]), "+f"(c[1]), "+f"(c[2]), "+f"(c[3])
        : "r"(a[0]), "r"(a[1]), "r"(a[2]), "r"(a[3]), "r"(b0), "r"(b1));
}

// window token (wi, n)  <->  flat index into the ORIGINAL x layout
__device__ __forceinline__ size_t win_to_src(int wi, int n) {
    int b  = wi >> 9;
    int l  = wi & 511;
    int wt = l >> 6, wh = (l >> 3) & 7, wwb = l & 7;
    int nt = n / 49, rem = n % 49, nh2 = rem / 7, nw2 = rem % 7;
    int ts = wt * 2 + nt, hs = wh * 7 + nh2, wsd = wwb * 7 + nw2;
    int t  = (ts + 1) & 15;
    int hh = hs + 3;  if (hh >= 56) hh -= 56;
    int ww = wsd + 3; if (ww >= 56) ww -= 56;
    return ((((size_t)b * 16 + t) * 56 + hh) * 56 + ww) * (size_t)CCH;
}

// ---------------------------------------------------------------- tf32 GEMM
// C[128x128 tile] = A[M x K] (f32 row-major) * Bt[N x K]^T, tf32 mma, f32 acc.
// 256 threads = 8 warps (4 in M x 2 in N); warp tile 32x64; mma m16n8k8.
// Smem rows pitch 36 words: bank(g*36+t mod 32) all distinct -> conflict-free.
__device__ __forceinline__ void mma_gemm(const float* __restrict__ A,
                                         const float* __restrict__ Bt,
                                         int K, int rowBase, int colBase,
                                         float acc[2][8][4]) {
    __shared__ u32 As[128][36];
    __shared__ u32 Bs[128][36];
    const int tid = threadIdx.x;
    const int lane = tid & 31, warp = tid >> 5;
    const int wm = warp & 3, wn = warp >> 2;
    const int g = lane >> 2, tg = lane & 3;
    const int lrow = tid >> 3;          // 0..31
    const int lcol = (tid & 7) * 4;     // 0..28

#pragma unroll
    for (int mf = 0; mf < 2; mf++)
#pragma unroll
        for (int nf = 0; nf < 8; nf++)
#pragma unroll
            for (int c = 0; c < 4; c++) acc[mf][nf][c] = 0.f;

    const float* Ab = A + (size_t)rowBase * K;
    const float* Bb = Bt + (size_t)colBase * K;

    for (int k0 = 0; k0 < K; k0 += 32) {
        uint4 ar[4], br[4];
#pragma unroll
        for (int qq = 0; qq < 4; qq++) {
            float4 av = *(const float4*)(Ab + (size_t)(lrow + qq * 32) * K + k0 + lcol);
            float4 bv = *(const float4*)(Bb + (size_t)(lrow + qq * 32) * K + k0 + lcol);
            ar[qq] = make_uint4(f2tf32(av.x), f2tf32(av.y), f2tf32(av.z), f2tf32(av.w));
            br[qq] = make_uint4(f2tf32(bv.x), f2tf32(bv.y), f2tf32(bv.z), f2tf32(bv.w));
        }
        __syncthreads();
#pragma unroll
        for (int qq = 0; qq < 4; qq++) {
            *(uint4*)&As[lrow + qq * 32][lcol] = ar[qq];
            *(uint4*)&Bs[lrow + qq * 32][lcol] = br[qq];
        }
        __syncthreads();
#pragma unroll
        for (int kk = 0; kk < 4; kk++) {
            const int kb = kk * 8;
            u32 af[2][4];
#pragma unroll
            for (int mf = 0; mf < 2; mf++) {
                int r0 = wm * 32 + mf * 16 + g;
                af[mf][0] = As[r0][kb + tg];
                af[mf][1] = As[r0 + 8][kb + tg];
                af[mf][2] = As[r0][kb + tg + 4];
                af[mf][3] = As[r0 + 8][kb + tg + 4];
            }
#pragma unroll
            for (int nf = 0; nf < 8; nf++) {
                int nb = wn * 64 + nf * 8 + g;
                u32 b0 = Bs[nb][kb + tg];
                u32 b1 = Bs[nb][kb + tg + 4];
                mma_tf32(acc[0][nf], af[0], b0, b1);
                mma_tf32(acc[1][nf], af[1], b0, b1);
            }
        }
    }
}

// ---------------------------------------------------------------- kernels
// Fused weight transpose for all four weights: dst[n*K + k] = W[k*N + n].
// Destinations are __device__ arrays referenced ONLY inside device code.
// (Passing a __device__ symbol as a host-side kernel argument hands the
// kernel the host shadow address — on GB300 (ATS) those writes silently land
// in host memory and the device buffer stays zero. Bug in rounds 5-14.)
// Block ranges: [0,192) qkv 49152, [192,256) proj 16384,
//               [256,512) fc1 65536, [512,768) fc2 65536.  256 thr/blk.
__global__ __launch_bounds__(256) void wprep_all(const float* __restrict__ w_qkv,
                                                 const float* __restrict__ w_proj,
                                                 const float* __restrict__ w_fc1,
                                                 const float* __restrict__ w_fc2) {
    int blk = blockIdx.x;
    const float* W; float* out; int K, N, base;
    if (blk < 192)      { W = w_qkv;  out = g_wqkvT;  K = 128; N = 384; base = 0;   }
    else if (blk < 256) { W = w_proj; out = g_wprojT; K = 128; N = 128; base = 192; }
    else if (blk < 512) { W = w_fc1;  out = g_wfc1T;  K = 128; N = 512; base = 256; }
    else                { W = w_fc2;  out = g_wfc2T;  K = 512; N = 128; base = 512; }
    int idx = (blk - base) * 256 + threadIdx.x;
    if (idx < K * N) {
        int k = idx / N, n = idx % N;
        out[n * K + k] = W[idx];
    }
}

__global__ void bias_kernel(const float* __restrict__ rpe, const int* __restrict__ idx) {
    int i = blockIdx.x * 256 + threadIdx.x;
    if (i < NHD * NTOK * NTOK) {
        int h = i / (NTOK * NTOK), e = i % (NTOK * NTOK);
        g_bias[i] = rpe[h * MREL + idx[e]];
    }
}

// LN1 + cyclic shift + window partition -> g_win. One warp per token.
__global__ __launch_bounds__(256) void ln1_kernel(const float* __restrict__ x,
                                                  const float* __restrict__ g,
                                                  const float* __restrict__ bb) {
    int warp = threadIdx.x >> 5, lane = threadIdx.x & 31;
    int tk = blockIdx.x * 8 + warp;
    int wi = tk / NTOK, n = tk % NTOK;
    const float* src = x + win_to_src(wi, n);
    float4 v = *(const float4*)(src + lane * 4);
    float s  = v.x + v.y + v.z + v.w;
    float sq = v.x * v.x + v.y * v.y + v.z * v.z + v.w * v.w;
#pragma unroll
    for (int o = 16; o; o >>= 1) {
        s  += __shfl_xor_sync(0xffffffffu, s, o);
        sq += __shfl_xor_sync(0xffffffffu, sq, o);
    }
    float mu = s * (1.0f / 128.0f);
    float var = sq * (1.0f / 128.0f) - mu * mu;
    float rstd = rsqrtf(var + 1e-5f);
    float4 gg = *(const float4*)(g + lane * 4);
    float4 b4 = *(const float4*)(bb + lane * 4);
    float4 o4;
    o4.x = (v.x - mu) * rstd * gg.x + b4.x;
    o4.y = (v.y - mu) * rstd * gg.y + b4.y;
    o4.z = (v.z - mu) * rstd * gg.z + b4.z;
    o4.w = (v.w - mu) * rstd * gg.w + b4.w;
    *(float4*)(g_win + (size_t)tk * CCH + lane * 4) = o4;
}

// QKV GEMM (tf32 mma): g_win @ wqkvT^T + b -> scatter q(scaled)/k/v
__global__ __launch_bounds__(256) void qkv_mma(const float* __restrict__ bias) {
    float acc[2][8][4];
    int rowBase = blockIdx.y * 128, colBase = blockIdx.x * 128;
    mma_gemm(g_win, g_wqkvT, 128, rowBase, colBase, acc);
    int lane = threadIdx.x & 31, warp = threadIdx.x >> 5;
    int wm = warp & 3, wn = warp >> 2;
#pragma unroll
    for (int mf = 0; mf < 2; mf++) {
#pragma unroll
        for (int rr = 0; rr < 2; rr++) {
            int row = rowBase + wm * 32 + mf * 16 + (lane >> 2) + rr * 8;
            int wi = row / NTOK, n = row % NTOK;
#pragma unroll
            for (int nf = 0; nf < 8; nf++) {
                int j = colBase + wn * 64 + nf * 8 + (lane & 3) * 2;
                float2 f;
                f.x = acc[mf][nf][rr * 2 + 0] + bias[j];
                f.y = acc[mf][nf][rr * 2 + 1] + bias[j + 1];
                int which = j >> 7, head = (j >> 5) & 3, hd = j & 31;
                size_t dst = ((size_t)((wi << 2) + head) * NTOK + n) * HDIM + hd;
                if (which == 0) {
                    f.x *= SCALE_Q; f.y *= SCALE_Q;
                    *(float2*)(g_q + dst) = f;
                } else if (which == 1) *(float2*)(g_k + dst) = f;
                else                   *(float2*)(g_v + dst) = f;
            }
        }
    }
}

// Attention per (window, head) — unchanged from the passing fp32 kernel.
__global__ __launch_bounds__(128) void attn_kernel(const float* __restrict__ amask) {
    __shared__ float qs[NTOK][32];
    __shared__ float ks[NTOK][36];
    __shared__ float vs[NTOK][32];
    __shared__ float ps[4][NTOK][4];

    int head = blockIdx.x, wi = blockIdx.y;
    int l = wi & 511;
    int tid = threadIdx.x, warp = tid >> 5, lane = tid & 31;
    size_t base = (size_t)((wi << 2) + head) * NTOK * HDIM;
    const float* qg = g_q + base;
    const float* kg = g_k + base;
    const float* vg = g_v + base;

    for (int i = tid; i < NTOK * 8; i += 128) {
        float4 qv = *(const float4*)(qg + i * 4);
        float4 kv = *(const float4*)(kg + i * 4);
        float4 vv = *(const float4*)(vg + i * 4);
        *(float4*)(&qs[0][0] + i * 4) = qv;
        *(float4*)(&vs[0][0] + i * 4) = vv;
        int m = i >> 3, dd = (i & 7) * 4;
        *(float4*)&ks[m][dd] = kv;
    }
    __syncthreads();

    const float* bm_b = g_bias + head * (NTOK * NTOK);
    const float* bm_m = amask + (size_t)l * (NTOK * NTOK);

    for (int gidx = warp; gidx < 25; gidx += 4) {
        int n0 = gidx * 4;
        ull accp[4][4];
#pragma unroll
        for (int r = 0; r < 4; r++)
#pragma unroll
            for (int mi = 0; mi < 4; mi++) accp[r][mi] = 0ULL;

#pragma unroll
        for (int d0 = 0; d0 < 8; d0++) {
            ulonglong2 q2[4];
#pragma unroll
            for (int r = 0; r < 4; r++) {
                int nc = n0 + r; if (nc > 97) nc = 97;
                q2[r] = *(const ulonglong2*)&qs[nc][d0 * 4];
            }
#pragma unroll
            for (int mi = 0; mi < 4; mi++) {
                int m = lane + (mi << 5);
                if (m < NTOK) {
                    ulonglong2 k2 = *(const ulonglong2*)&ks[m][d0 * 4];
#pragma unroll
                    for (int r = 0; r < 4; r++) {
                        ffma2(accp[r][mi], q2[r].x, k2.x);
                        ffma2(accp[r][mi], q2[r].y, k2.y);
                    }
                }
            }
        }

#pragma unroll
        for (int r = 0; r < 4; r++) {
            int n = n0 + r;
            if (n < NTOK) {
                float sc[4];
#pragma unroll
                for (int mi = 0; mi < 4; mi++) {
                    int m = lane + (mi << 5);
                    if (m < NTOK) {
                        float2 f = unpack2(accp[r][mi]);
                        sc[mi] = f.x + f.y + bm_b[n * NTOK + m] + bm_m[n * NTOK + m];
                    } else sc[mi] = -1e30f;
                }
                float mx = fmaxf(fmaxf(sc[0], sc[1]), fmaxf(sc[2], sc[3]));
#pragma unroll
                for (int o = 16; o; o >>= 1) mx = fmaxf(mx, __shfl_xor_sync(0xffffffffu, mx, o));
                float ssum = 0.f;
#pragma unroll
                for (int mi = 0; mi < 4; mi++) {
                    int m = lane + (mi << 5);
                    if (m < NTOK) { float e = __expf(sc[mi] - mx); sc[mi] = e; ssum += e; }
                }
#pragma unroll
                for (int o = 16; o; o >>= 1) ssum += __shfl_xor_sync(0xffffffffu, ssum, o);
                float inv = 1.0f / ssum;
#pragma unroll
                for (int mi = 0; mi < 4; mi++) {
                    int m = lane + (mi << 5);
                    if (m < NTOK) ps[warp][m][r] = sc[mi] * inv;
                }
            } else {
#pragma unroll
                for (int mi = 0; mi < 4; mi++) {
                    int m = lane + (mi << 5);
                    if (m < NTOK) ps[warp][m][r] = 0.f;
                }
            }
        }
        __syncwarp();

        ull o2a = 0ULL, o2b = 0ULL;
        for (int m = 0; m < NTOK; m++) {
            float vv = vs[m][lane];
            ulonglong2 pp = *(const ulonglong2*)&ps[warp][m][0];
            ull v2 = pack2(vv);
            ffma2(o2a, pp.x, v2);
            ffma2(o2b, pp.y, v2);
        }
        float2 oa = unpack2(o2a), ob = unpack2(o2b);
        float ov[4] = {oa.x, oa.y, ob.x, ob.y};
#pragma unroll
        for (int r = 0; r < 4; r++) {
            int n = n0 + r;
            if (n < NTOK)
                g_win[((size_t)wi * NTOK + n) * CCH + head * HDIM + lane] = ov[r];
        }
        __syncwarp();
    }
}

// proj GEMM + un-partition + reverse shift + residual -> g_xres
__global__ __launch_bounds__(256) void proj_mma(const float* __restrict__ bias,
                                                const float* __restrict__ x) {
    float acc[2][8][4];
    int rowBase = blockIdx.y * 128;
    mma_gemm(g_win, g_wprojT, 128, rowBase, 0, acc);
    int lane = threadIdx.x & 31, warp = threadIdx.x >> 5;
    int wm = warp & 3, wn = warp >> 2;
#pragma unroll
    for (int mf = 0; mf < 2; mf++) {
#pragma unroll
        for (int rr = 0; rr < 2; rr++) {
            int row = rowBase + wm * 32 + mf * 16 + (lane >> 2) + rr * 8;
            int wi = row / NTOK, n = row % NTOK;
            size_t dst = win_to_src(wi, n);
#pragma unroll
            for (int nf = 0; nf < 8; nf++) {
                int j = wn * 64 + nf * 8 + (lane & 3) * 2;
                float2 xr = *(const float2*)(x + dst + j);
                float2 o;
                o.x = xr.x + acc[mf][nf][rr * 2 + 0] + bias[j];
                o.y = xr.y + acc[mf][nf][rr * 2 + 1] + bias[j + 1];
                *(float2*)(g_xres + dst + j) = o;
            }
        }
    }
}

// LN2: g_xres -> g_q (reused as xn2), natural token order
__global__ __launch_bounds__(256) void ln2_kernel(const float* __restrict__ g,
                                                  const float* __restrict__ bb) {
    int warp = threadIdx.x >> 5, lane = threadIdx.x & 31;
    int tk = blockIdx.x * 8 + warp;
    const float* src = g_xres + (size_t)tk * CCH;
    float4 v = *(const float4*)(src + lane * 4);
    float s  = v.x + v.y + v.z + v.w;
    float sq = v.x * v.x + v.y * v.y + v.z * v.z + v.w * v.w;
#pragma unroll
    for (int o = 16; o; o >>= 1) {
        s  += __shfl_xor_sync(0xffffffffu, s, o);
        sq += __shfl_xor_sync(0xffffffffu, sq, o);
    }
    float mu = s * (1.0f / 128.0f);
    float var = sq * (1.0f / 128.0f) - mu * mu;
    float rstd = rsqrtf(var + 1e-5f);
    float4 gg = *(const float4*)(g + lane * 4);
    float4 b4 = *(const float4*)(bb + lane * 4);
    float4 o4;
    o4.x = (v.x - mu) * rstd * gg.x + b4.x;
    o4.y = (v.y - mu) * rstd * gg.y + b4.y;
    o4.z = (v.z - mu) * rstd * gg.z + b4.z;
    o4.w = (v.w - mu) * rstd * gg.w + b4.w;
    *(float4*)(g_q + (size_t)tk * CCH + lane * 4) = o4;
}

// FC1 GEMM + exact GELU -> g_h
__global__ __launch_bounds__(256) void fc1_mma(const float* __restrict__ bias) {
    float acc[2][8][4];
    int rowBase = blockIdx.y * 128, colBase = blockIdx.x * 128;
    mma_gemm(g_q, g_wfc1T, 128, rowBase, colBase, acc);
    int lane = threadIdx.x & 31, warp = threadIdx.x >> 5;
    int wm = warp & 3, wn = warp >> 2;
#pragma unroll
    for (int mf = 0; mf < 2; mf++) {
#pragma unroll
        for (int rr = 0; rr < 2; rr++) {
            int row = rowBase + wm * 32 + mf * 16 + (lane >> 2) + rr * 8;
            float* hrow = g_h + (size_t)row * MLPH;
#pragma unroll
            for (int nf = 0; nf < 8; nf++) {
                int j = colBase + wn * 64 + nf * 8 + (lane & 3) * 2;
                float2 o;
                o.x = gelu_f(acc[mf][nf][rr * 2 + 0] + bias[j]);
                o.y = gelu_f(acc[mf][nf][rr * 2 + 1] + bias[j + 1]);
                *(float2*)(hrow + j) = o;
            }
        }
    }
}

// FC2 GEMM (K=512) + final residual -> d_out
__global__ __launch_bounds__(256) void fc2_mma(const float* __restrict__ bias,
                                               float* __restrict__ out) {
    float acc[2][8][4];
    int rowBase = blockIdx.y * 128;
    mma_gemm(g_h, g_wfc2T, 512, rowBase, 0, acc);
    int lane = threadIdx.x & 31, warp = threadIdx.x >> 5;
    int wm = warp & 3, wn = warp >> 2;
#pragma unroll
    for (int mf = 0; mf < 2; mf++) {
#pragma unroll
        for (int rr = 0; rr < 2; rr++) {
            int row = rowBase + wm * 32 + mf * 16 + (lane >> 2) + rr * 8;
            size_t off = (size_t)row * CCH;
#pragma unroll
            for (int nf = 0; nf < 8; nf++) {
                int j = wn * 64 + nf * 8 + (lane & 3) * 2;
                float2 xr = *(const float2*)(g_xres + off + j);
                float2 o;
                o.x = xr.x + acc[mf][nf][rr * 2 + 0] + bias[j];
                o.y = xr.y + acc[mf][nf][rr * 2 + 1] + bias[j + 1];
                *(float2*)(out + off + j) = o;
            }
        }
    }
}

// ---------------------------------------------------------------- launch
extern "C" void kernel_launch(void* const* d_in, const int* in_sizes, int n_in,
                              void* d_out, int out_size) {
    const float* x      = (const float*)d_in[0];
    const float* g1     = (const float*)d_in[1];
    const float* b1     = (const float*)d_in[2];
    const float* w_qkv  = (const float*)d_in[3];
    const float* b_qkv  = (const float*)d_in[4];
    const float* rpe    = (const float*)d_in[5];
    const float* w_proj = (const float*)d_in[6];
    const float* b_proj = (const float*)d_in[7];
    const float* g2     = (const float*)d_in[8];
    const float* b2     = (const float*)d_in[9];
    const float* w_fc1  = (const float*)d_in[10];
    const float* b_fc1  = (const float*)d_in[11];
    const float* w_fc2  = (const float*)d_in[12];
    const float* b_fc2  = (const float*)d_in[13];
    const float* amask  = (const float*)d_in[14];
    const int*   rpidx  = (const int*)d_in[15];
    float* out = (float*)d_out;

    wprep_all<<<768, 256>>>(w_qkv, w_proj, w_fc1, w_fc2);
    bias_kernel<<<(NHD * NTOK * NTOK + 255) / 256, 256>>>(rpe, rpidx);

    ln1_kernel<<<MTOT / 8, 256>>>(x, g1, b1);
    qkv_mma<<<dim3(3, MTOT / 128), 256>>>(b_qkv);
    attn_kernel<<<dim3(NHD, NWIN), 128>>>(amask);
    proj_mma<<<dim3(1, MTOT / 128), 256>>>(b_proj, x);
    ln2_kernel<<<MTOT / 8, 256>>>(g2, b2);
    fc1_mma<<<dim3(4, MTOT / 128), 256>>>(b_fc1);
    fc2_mma<<<dim3(1, MTOT / 128), 256>>>(b_fc2, out);
}

// round 17
// speedup vs baseline: 2.7546x; 1.0693x over previous
#include <cuda_runtime.h>

typedef unsigned long long ull;
typedef unsigned int u32;

// ---------------------------------------------------------------- constants
#define MTOT 200704          // total tokens = 4*16*56*56 = 2048 windows * 98
#define NWIN 2048
#define NTOK 98
#define CCH  128
#define NHD  4
#define HDIM 32
#define MREL 507
#define MLPH 512
#define SCALE_Q 0.17677669529663687f   // 32^-0.5

#define SPITCH 36                       // smem row pitch (words)
#define TILE_WORDS (128 * SPITCH)       // one 128x32 tile, padded
#define SMEM_DB_BYTES (4 * TILE_WORDS * 4)  // A[2] + B[2] buffers = 73728 B

// ---------------------------------------------------------------- scratch
// g_win: LN1 output (window order), then attention output
// g_q  : scaled Q, then LN2 output (xn2)
__device__ __align__(16) float g_win[MTOT * CCH];
__device__ __align__(16) float g_q[MTOT * CCH];
__device__ __align__(16) float g_k[MTOT * CCH];
__device__ __align__(16) float g_v[MTOT * CCH];
__device__ __align__(16) float g_xres[MTOT * CCH];
__device__ __align__(16) float g_h[MTOT * MLPH];
__device__ __align__(16) float g_bias[NHD * NTOK * NTOK];
// fp32 transposed weights [N][K]
__device__ __align__(16) float g_wqkvT[384 * 128];
__device__ __align__(16) float g_wprojT[128 * 128];
__device__ __align__(16) float g_wfc1T[512 * 128];
__device__ __align__(16) float g_wfc2T[128 * 512];

// ---------------------------------------------------------------- helpers
__device__ __forceinline__ ull pack2(float a) {
    ull r; asm("mov.b64 %0, {%1, %1};" : "=l"(r) : "f"(a)); return r;
}
__device__ __forceinline__ float2 unpack2(ull v) {
    float2 f; asm("mov.b64 {%0, %1}, %2;" : "=f"(f.x), "=f"(f.y) : "l"(v)); return f;
}
__device__ __forceinline__ void ffma2(ull &acc, ull a, ull b) {
    asm("fma.rn.f32x2 %0, %1, %2, %0;" : "+l"(acc) : "l"(a), "l"(b));
}
__device__ __forceinline__ float gelu_f(float v) {
    return 0.5f * v * (1.0f + erff(v * 0.70710678118654752f));
}
__device__ __forceinline__ void mma_tf32(float c[4], const u32 a[4],
                                         u32 b0, u32 b1) {
    asm("mma.sync.aligned.m16n8k8.row.col.f32.tf32.tf32.f32 "
        "{%0,%1,%2,%3}, {%4,%5,%6,%7}, {%8,%9}, {%0,%1,%2,%3};"
        : "+f"(c[0]), "+f"(c[1]), "+f"(c[2]), "+f"(c[3])
        : "r"(a[0]), "r"(a[1]), "r"(a[2]), "r"(a[3]), "r"(b0), "r"(b1));
}
__device__ __forceinline__ void cp_async16(u32 saddr, const void* gptr) {
    asm volatile("cp.async.ca.shared.global [%0], [%1], 16;"
                 :: "r"(saddr), "l"(gptr));
}
#define CP_COMMIT() asm volatile("cp.async.commit_group;" ::: "memory")
#define CP_WAIT1()  asm volatile("cp.async.wait_group 1;" ::: "memory")
#define CP_WAIT0()  asm volatile("cp.async.wait_group 0;" ::: "memory")

// window token (wi, n)  <->  flat index into the ORIGINAL x layout
__device__ __forceinline__ size_t win_to_src(int wi, int n) {
    int b  = wi >> 9;
    int l  = wi & 511;
    int wt = l >> 6, wh = (l >> 3) & 7, wwb = l & 7;
    int nt = n / 49, rem = n % 49, nh2 = rem / 7, nw2 = rem % 7;
    int ts = wt * 2 + nt, hs = wh * 7 + nh2, wsd = wwb * 7 + nw2;
    int t  = (ts + 1) & 15;
    int hh = hs + 3;  if (hh >= 56) hh -= 56;
    int ww = wsd + 3; if (ww >= 56) ww -= 56;
    return ((((size_t)b * 16 + t) * 56 + hh) * 56 + ww) * (size_t)CCH;
}

// ---------------------------------------------------------------- tf32 GEMM
// C[128x128 tile] = A[M x K] (f32 row-major) * Bt[N x K]^T, tf32 mma, f32 acc.
// 256 threads = 8 warps (4 in M x 2 in N); warp tile 32x64; mma m16n8k8.
// cp.async double-buffered mainloop: raw fp32 bits fed to HMMA (HW truncates
// mantissa to tf32 — CUTLASS-standard path, no cvt needed).
// Smem pitch 36 words: fragment reads conflict-free (4g+tg distinct mod 32).
__device__ __forceinline__ void mma_gemm(const float* __restrict__ A,
                                         const float* __restrict__ Bt,
                                         int K, int rowBase, int colBase,
                                         float acc[2][8][4]) {
    extern __shared__ u32 sm[];
    u32* As = sm;                    // [2][128][SPITCH]
    u32* Bs = sm + 2 * TILE_WORDS;   // [2][128][SPITCH]
    const int tid = threadIdx.x;
    const int lane = tid & 31, warp = tid >> 5;
    const int wm = warp & 3, wn = warp >> 2;
    const int g = lane >> 2, tg = lane & 3;
    const int lrow = tid >> 3;          // 0..31
    const int lcol = (tid & 7) * 4;     // 0..28

#pragma unroll
    for (int mf = 0; mf < 2; mf++)
#pragma unroll
        for (int nf = 0; nf < 8; nf++)
#pragma unroll
            for (int c = 0; c < 4; c++) acc[mf][nf][c] = 0.f;

    const float* Ab = A + (size_t)rowBase * K;
    const float* Bb = Bt + (size_t)colBase * K;
    u32 as_base = (u32)__cvta_generic_to_shared(As);
    u32 bs_base = (u32)__cvta_generic_to_shared(Bs);
    const int nk = K >> 5;

    // prologue: stage k-chunk 0 into buffer 0
#pragma unroll
    for (int qq = 0; qq < 4; qq++) {
        int row = lrow + qq * 32;
        u32 so = (u32)(row * SPITCH + lcol) * 4;
        cp_async16(as_base + so, Ab + (size_t)row * K + lcol);
        cp_async16(bs_base + so, Bb + (size_t)row * K + lcol);
    }
    CP_COMMIT();

    for (int it = 0; it < nk; it++) {
        int buf = it & 1;
        if (it + 1 < nk) {
            int k0 = (it + 1) << 5;
            u32 bo = (u32)((buf ^ 1) * TILE_WORDS) * 4;
#pragma unroll
            for (int qq = 0; qq < 4; qq++) {
                int row = lrow + qq * 32;
                u32 so = bo + (u32)(row * SPITCH + lcol) * 4;
                cp_async16(as_base + so, Ab + (size_t)row * K + k0 + lcol);
                cp_async16(bs_base + so, Bb + (size_t)row * K + k0 + lcol);
            }
            CP_COMMIT();
            CP_WAIT1();
        } else {
            CP_WAIT0();
        }
        __syncthreads();

        const u32* Ac = As + buf * TILE_WORDS;
        const u32* Bc = Bs + buf * TILE_WORDS;
#pragma unroll
        for (int kk = 0; kk < 4; kk++) {
            const int kb = kk * 8;
            u32 af[2][4];
#pragma unroll
            for (int mf = 0; mf < 2; mf++) {
                int r0 = wm * 32 + mf * 16 + g;
                af[mf][0] = Ac[r0 * SPITCH + kb + tg];
                af[mf][1] = Ac[(r0 + 8) * SPITCH + kb + tg];
                af[mf][2] = Ac[r0 * SPITCH + kb + tg + 4];
                af[mf][3] = Ac[(r0 + 8) * SPITCH + kb + tg + 4];
            }
#pragma unroll
            for (int nf = 0; nf < 8; nf++) {
                int nb = wn * 64 + nf * 8 + g;
                u32 b0 = Bc[nb * SPITCH + kb + tg];
                u32 b1 = Bc[nb * SPITCH + kb + tg + 4];
                mma_tf32(acc[0][nf], af[0], b0, b1);
                mma_tf32(acc[1][nf], af[1], b0, b1);
            }
        }
        __syncthreads();
    }
}

// ---------------------------------------------------------------- kernels
// Fused weight transpose for all four weights: dst[n*K + k] = W[k*N + n].
// Destinations are __device__ arrays referenced ONLY inside device code.
// (Passing a __device__ symbol as a host-side kernel argument hands the
// kernel the host shadow address — on GB300 (ATS) those writes silently land
// in host memory and the device buffer stays zero. Bug in rounds 5-14.)
__global__ __launch_bounds__(256) void wprep_all(const float* __restrict__ w_qkv,
                                                 const float* __restrict__ w_proj,
                                                 const float* __restrict__ w_fc1,
                                                 const float* __restrict__ w_fc2) {
    int blk = blockIdx.x;
    const float* W; float* out; int K, N, base;
    if (blk < 192)      { W = w_qkv;  out = g_wqkvT;  K = 128; N = 384; base = 0;   }
    else if (blk < 256) { W = w_proj; out = g_wprojT; K = 128; N = 128; base = 192; }
    else if (blk < 512) { W = w_fc1;  out = g_wfc1T;  K = 128; N = 512; base = 256; }
    else                { W = w_fc2;  out = g_wfc2T;  K = 512; N = 128; base = 512; }
    int idx = (blk - base) * 256 + threadIdx.x;
    if (idx < K * N) {
        int k = idx / N, n = idx % N;
        out[n * K + k] = W[idx];
    }
}

__global__ void bias_kernel(const float* __restrict__ rpe, const int* __restrict__ idx) {
    int i = blockIdx.x * 256 + threadIdx.x;
    if (i < NHD * NTOK * NTOK) {
        int h = i / (NTOK * NTOK), e = i % (NTOK * NTOK);
        g_bias[i] = rpe[h * MREL + idx[e]];
    }
}

// LN1 + cyclic shift + window partition -> g_win. One warp per token.
__global__ __launch_bounds__(256) void ln1_kernel(const float* __restrict__ x,
                                                  const float* __restrict__ g,
                                                  const float* __restrict__ bb) {
    int warp = threadIdx.x >> 5, lane = threadIdx.x & 31;
    int tk = blockIdx.x * 8 + warp;
    int wi = tk / NTOK, n = tk % NTOK;
    const float* src = x + win_to_src(wi, n);
    float4 v = *(const float4*)(src + lane * 4);
    float s  = v.x + v.y + v.z + v.w;
    float sq = v.x * v.x + v.y * v.y + v.z * v.z + v.w * v.w;
#pragma unroll
    for (int o = 16; o; o >>= 1) {
        s  += __shfl_xor_sync(0xffffffffu, s, o);
        sq += __shfl_xor_sync(0xffffffffu, sq, o);
    }
    float mu = s * (1.0f / 128.0f);
    float var = sq * (1.0f / 128.0f) - mu * mu;
    float rstd = rsqrtf(var + 1e-5f);
    float4 gg = *(const float4*)(g + lane * 4);
    float4 b4 = *(const float4*)(bb + lane * 4);
    float4 o4;
    o4.x = (v.x - mu) * rstd * gg.x + b4.x;
    o4.y = (v.y - mu) * rstd * gg.y + b4.y;
    o4.z = (v.z - mu) * rstd * gg.z + b4.z;
    o4.w = (v.w - mu) * rstd * gg.w + b4.w;
    *(float4*)(g_win + (size_t)tk * CCH + lane * 4) = o4;
}

// QKV GEMM (tf32 mma): g_win @ wqkvT^T + b -> scatter q(scaled)/k/v
__global__ __launch_bounds__(256) void qkv_mma(const float* __restrict__ bias) {
    float acc[2][8][4];
    int rowBase = blockIdx.y * 128, colBase = blockIdx.x * 128;
    mma_gemm(g_win, g_wqkvT, 128, rowBase, colBase, acc);
    int lane = threadIdx.x & 31, warp = threadIdx.x >> 5;
    int wm = warp & 3, wn = warp >> 2;
#pragma unroll
    for (int mf = 0; mf < 2; mf++) {
#pragma unroll
        for (int rr = 0; rr < 2; rr++) {
            int row = rowBase + wm * 32 + mf * 16 + (lane >> 2) + rr * 8;
            int wi = row / NTOK, n = row % NTOK;
#pragma unroll
            for (int nf = 0; nf < 8; nf++) {
                int j = colBase + wn * 64 + nf * 8 + (lane & 3) * 2;
                float2 f;
                f.x = acc[mf][nf][rr * 2 + 0] + bias[j];
                f.y = acc[mf][nf][rr * 2 + 1] + bias[j + 1];
                int which = j >> 7, head = (j >> 5) & 3, hd = j & 31;
                size_t dst = ((size_t)((wi << 2) + head) * NTOK + n) * HDIM + hd;
                if (which == 0) {
                    f.x *= SCALE_Q; f.y *= SCALE_Q;
                    *(float2*)(g_q + dst) = f;
                } else if (which == 1) *(float2*)(g_k + dst) = f;
                else                   *(float2*)(g_v + dst) = f;
            }
        }
    }
}

// Attention per (window, head) — unchanged from the passing fp32 kernel.
__global__ __launch_bounds__(128) void attn_kernel(const float* __restrict__ amask) {
    __shared__ float qs[NTOK][32];
    __shared__ float ks[NTOK][36];
    __shared__ float vs[NTOK][32];
    __shared__ float ps[4][NTOK][4];

    int head = blockIdx.x, wi = blockIdx.y;
    int l = wi & 511;
    int tid = threadIdx.x, warp = tid >> 5, lane = tid & 31;
    size_t base = (size_t)((wi << 2) + head) * NTOK * HDIM;
    const float* qg = g_q + base;
    const float* kg = g_k + base;
    const float* vg = g_v + base;

    for (int i = tid; i < NTOK * 8; i += 128) {
        float4 qv = *(const float4*)(qg + i * 4);
        float4 kv = *(const float4*)(kg + i * 4);
        float4 vv = *(const float4*)(vg + i * 4);
        *(float4*)(&qs[0][0] + i * 4) = qv;
        *(float4*)(&vs[0][0] + i * 4) = vv;
        int m = i >> 3, dd = (i & 7) * 4;
        *(float4*)&ks[m][dd] = kv;
    }
    __syncthreads();

    const float* bm_b = g_bias + head * (NTOK * NTOK);
    const float* bm_m = amask + (size_t)l * (NTOK * NTOK);

    for (int gidx = warp; gidx < 25; gidx += 4) {
        int n0 = gidx * 4;
        ull accp[4][4];
#pragma unroll
        for (int r = 0; r < 4; r++)
#pragma unroll
            for (int mi = 0; mi < 4; mi++) accp[r][mi] = 0ULL;

#pragma unroll
        for (int d0 = 0; d0 < 8; d0++) {
            ulonglong2 q2[4];
#pragma unroll
            for (int r = 0; r < 4; r++) {
                int nc = n0 + r; if (nc > 97) nc = 97;
                q2[r] = *(const ulonglong2*)&qs[nc][d0 * 4];
            }
#pragma unroll
            for (int mi = 0; mi < 4; mi++) {
                int m = lane + (mi << 5);
                if (m < NTOK) {
                    ulonglong2 k2 = *(const ulonglong2*)&ks[m][d0 * 4];
#pragma unroll
                    for (int r = 0; r < 4; r++) {
                        ffma2(accp[r][mi], q2[r].x, k2.x);
                        ffma2(accp[r][mi], q2[r].y, k2.y);
                    }
                }
            }
        }

#pragma unroll
        for (int r = 0; r < 4; r++) {
            int n = n0 + r;
            if (n < NTOK) {
                float sc[4];
#pragma unroll
                for (int mi = 0; mi < 4; mi++) {
                    int m = lane + (mi << 5);
                    if (m < NTOK) {
                        float2 f = unpack2(accp[r][mi]);
                        sc[mi] = f.x + f.y + bm_b[n * NTOK + m] + bm_m[n * NTOK + m];
                    } else sc[mi] = -1e30f;
                }
                float mx = fmaxf(fmaxf(sc[0], sc[1]), fmaxf(sc[2], sc[3]));
#pragma unroll
                for (int o = 16; o; o >>= 1) mx = fmaxf(mx, __shfl_xor_sync(0xffffffffu, mx, o));
                float ssum = 0.f;
#pragma unroll
                for (int mi = 0; mi < 4; mi++) {
                    int m = lane + (mi << 5);
                    if (m < NTOK) { float e = __expf(sc[mi] - mx); sc[mi] = e; ssum += e; }
                }
#pragma unroll
                for (int o = 16; o; o >>= 1) ssum += __shfl_xor_sync(0xffffffffu, ssum, o);
                float inv = 1.0f / ssum;
#pragma unroll
                for (int mi = 0; mi < 4; mi++) {
                    int m = lane + (mi << 5);
                    if (m < NTOK) ps[warp][m][r] = sc[mi] * inv;
                }
            } else {
#pragma unroll
                for (int mi = 0; mi < 4; mi++) {
                    int m = lane + (mi << 5);
                    if (m < NTOK) ps[warp][m][r] = 0.f;
                }
            }
        }
        __syncwarp();

        ull o2a = 0ULL, o2b = 0ULL;
        for (int m = 0; m < NTOK; m++) {
            float vv = vs[m][lane];
            ulonglong2 pp = *(const ulonglong2*)&ps[warp][m][0];
            ull v2 = pack2(vv);
            ffma2(o2a, pp.x, v2);
            ffma2(o2b, pp.y, v2);
        }
        float2 oa = unpack2(o2a), ob = unpack2(o2b);
        float ov[4] = {oa.x, oa.y, ob.x, ob.y};
#pragma unroll
        for (int r = 0; r < 4; r++) {
            int n = n0 + r;
            if (n < NTOK)
                g_win[((size_t)wi * NTOK + n) * CCH + head * HDIM + lane] = ov[r];
        }
        __syncwarp();
    }
}

// proj GEMM + un-partition + reverse shift + residual -> g_xres
__global__ __launch_bounds__(256) void proj_mma(const float* __restrict__ bias,
                                                const float* __restrict__ x) {
    float acc[2][8][4];
    int rowBase = blockIdx.y * 128;
    mma_gemm(g_win, g_wprojT, 128, rowBase, 0, acc);
    int lane = threadIdx.x & 31, warp = threadIdx.x >> 5;
    int wm = warp & 3, wn = warp >> 2;
#pragma unroll
    for (int mf = 0; mf < 2; mf++) {
#pragma unroll
        for (int rr = 0; rr < 2; rr++) {
            int row = rowBase + wm * 32 + mf * 16 + (lane >> 2) + rr * 8;
            int wi = row / NTOK, n = row % NTOK;
            size_t dst = win_to_src(wi, n);
#pragma unroll
            for (int nf = 0; nf < 8; nf++) {
                int j = wn * 64 + nf * 8 + (lane & 3) * 2;
                float2 xr = *(const float2*)(x + dst + j);
                float2 o;
                o.x = xr.x + acc[mf][nf][rr * 2 + 0] + bias[j];
                o.y = xr.y + acc[mf][nf][rr * 2 + 1] + bias[j + 1];
                *(float2*)(g_xres + dst + j) = o;
            }
        }
    }
}

// LN2: g_xres -> g_q (reused as xn2), natural token order
__global__ __launch_bounds__(256) void ln2_kernel(const float* __restrict__ g,
                                                  const float* __restrict__ bb) {
    int warp = threadIdx.x >> 5, lane = threadIdx.x & 31;
    int tk = blockIdx.x * 8 + warp;
    const float* src = g_xres + (size_t)tk * CCH;
    float4 v = *(const float4*)(src + lane * 4);
    float s  = v.x + v.y + v.z + v.w;
    float sq = v.x * v.x + v.y * v.y + v.z * v.z + v.w * v.w;
#pragma unroll
    for (int o = 16; o; o >>= 1) {
        s  += __shfl_xor_sync(0xffffffffu, s, o);
        sq += __shfl_xor_sync(0xffffffffu, sq, o);
    }
    float mu = s * (1.0f / 128.0f);
    float var = sq * (1.0f / 128.0f) - mu * mu;
    float rstd = rsqrtf(var + 1e-5f);
    float4 gg = *(const float4*)(g + lane * 4);
    float4 b4 = *(const float4*)(bb + lane * 4);
    float4 o4;
    o4.x = (v.x - mu) * rstd * gg.x + b4.x;
    o4.y = (v.y - mu) * rstd * gg.y + b4.y;
    o4.z = (v.z - mu) * rstd * gg.z + b4.z;
    o4.w = (v.w - mu) * rstd * gg.w + b4.w;
    *(float4*)(g_q + (size_t)tk * CCH + lane * 4) = o4;
}

// FC1 GEMM + exact GELU -> g_h
__global__ __launch_bounds__(256) void fc1_mma(const float* __restrict__ bias) {
    float acc[2][8][4];
    int rowBase = blockIdx.y * 128, colBase = blockIdx.x * 128;
    mma_gemm(g_q, g_wfc1T, 128, rowBase, colBase, acc);
    int lane = threadIdx.x & 31, warp = threadIdx.x >> 5;
    int wm = warp & 3, wn = warp >> 2;
#pragma unroll
    for (int mf = 0; mf < 2; mf++) {
#pragma unroll
        for (int rr = 0; rr < 2; rr++) {
            int row = rowBase + wm * 32 + mf * 16 + (lane >> 2) + rr * 8;
            float* hrow = g_h + (size_t)row * MLPH;
#pragma unroll
            for (int nf = 0; nf < 8; nf++) {
                int j = colBase + wn * 64 + nf * 8 + (lane & 3) * 2;
                float2 o;
                o.x = gelu_f(acc[mf][nf][rr * 2 + 0] + bias[j]);
                o.y = gelu_f(acc[mf][nf][rr * 2 + 1] + bias[j + 1]);
                *(float2*)(hrow + j) = o;
            }
        }
    }
}

// FC2 GEMM (K=512) + final residual -> d_out
__global__ __launch_bounds__(256) void fc2_mma(const float* __restrict__ bias,
                                               float* __restrict__ out) {
    float acc[2][8][4];
    int rowBase = blockIdx.y * 128;
    mma_gemm(g_h, g_wfc2T, 512, rowBase, 0, acc);
    int lane = threadIdx.x & 31, warp = threadIdx.x >> 5;
    int wm = warp & 3, wn = warp >> 2;
#pragma unroll
    for (int mf = 0; mf < 2; mf++) {
#pragma unroll
        for (int rr = 0; rr < 2; rr++) {
            int row = rowBase + wm * 32 + mf * 16 + (lane >> 2) + rr * 8;
            size_t off = (size_t)row * CCH;
#pragma unroll
            for (int nf = 0; nf < 8; nf++) {
                int j = wn * 64 + nf * 8 + (lane & 3) * 2;
                float2 xr = *(const float2*)(g_xres + off + j);
                float2 o;
                o.x = xr.x + acc[mf][nf][rr * 2 + 0] + bias[j];
                o.y = xr.y + acc[mf][nf][rr * 2 + 1] + bias[j + 1];
                *(float2*)(out + off + j) = o;
            }
        }
    }
}

// ---------------------------------------------------------------- launch
extern "C" void kernel_launch(void* const* d_in, const int* in_sizes, int n_in,
                              void* d_out, int out_size) {
    const float* x      = (const float*)d_in[0];
    const float* g1     = (const float*)d_in[1];
    const float* b1     = (const float*)d_in[2];
    const float* w_qkv  = (const float*)d_in[3];
    const float* b_qkv  = (const float*)d_in[4];
    const float* rpe    = (const float*)d_in[5];
    const float* w_proj = (const float*)d_in[6];
    const float* b_proj = (const float*)d_in[7];
    const float* g2     = (const float*)d_in[8];
    const float* b2     = (const float*)d_in[9];
    const float* w_fc1  = (const float*)d_in[10];
    const float* b_fc1  = (const float*)d_in[11];
    const float* w_fc2  = (const float*)d_in[12];
    const float* b_fc2  = (const float*)d_in[13];
    const float* amask  = (const float*)d_in[14];
    const int*   rpidx  = (const int*)d_in[15];
    float* out = (float*)d_out;

    // opt-in to 72KB dynamic smem for the GEMM kernels (not an allocation;
    // executes immediately, legal under graph capture)
    cudaFuncSetAttribute(qkv_mma,  cudaFuncAttributeMaxDynamicSharedMemorySize, SMEM_DB_BYTES);
    cudaFuncSetAttribute(proj_mma, cudaFuncAttributeMaxDynamicSharedMemorySize, SMEM_DB_BYTES);
    cudaFuncSetAttribute(fc1_mma,  cudaFuncAttributeMaxDynamicSharedMemorySize, SMEM_DB_BYTES);
    cudaFuncSetAttribute(fc2_mma,  cudaFuncAttributeMaxDynamicSharedMemorySize, SMEM_DB_BYTES);

    wprep_all<<<768, 256>>>(w_qkv, w_proj, w_fc1, w_fc2);
    bias_kernel<<<(NHD * NTOK * NTOK + 255) / 256, 256>>>(rpe, rpidx);

    ln1_kernel<<<MTOT / 8, 256>>>(x, g1, b1);
    qkv_mma<<<dim3(3, MTOT / 128), 256, SMEM_DB_BYTES>>>(b_qkv);
    attn_kernel<<<dim3(NHD, NWIN), 128>>>(amask);
    proj_mma<<<dim3(1, MTOT / 128), 256, SMEM_DB_BYTES>>>(b_proj, x);
    ln2_kernel<<<MTOT / 8, 256>>>(g2, b2);
    fc1_mma<<<dim3(4, MTOT / 128), 256, SMEM_DB_BYTES>>>(b_fc1);
    fc2_mma<<<dim3(1, MTOT / 128), 256, SMEM_DB_BYTES>>>(b_fc2, out);
}